// round 1
// baseline (speedup 1.0000x reference)
#include <cuda_runtime.h>
#include <cstdint>

// Problem constants
#define BB 4
#define CC 256
#define FF 16
#define PP 1024                 // H*W
#define NN 64                   // B*F
#define CP (CC*PP)              // 262144, per-n slice elems
#define CFP (CC*FF*PP)          // 4194304, per-b elems in x layout

// Scratch for projections (allocation-guard-safe static device arrays): 3 x 64 MB
__device__ float g_q[(size_t)NN*CP];
__device__ float g_k[(size_t)NN*CP];
__device__ float g_v[(size_t)NN*CP];

#define FMA2(acc, a, b) asm("fma.rn.f32x2 %0, %1, %2, %3;" : "=l"(acc) : "l"(a), "l"(b), "l"(acc))

// ---------------------------------------------------------------------------
// Pass 1: fused QKV projection GEMM.
// For each n in [0,64): Y[d,p] = sum_c W[d,c] * X[n][c,p] + bias[d]
// Tile: BM=64 (d), BN=64 (p), BK=16 (c). 256 threads, each owns 4 d x 4 p
// per matrix, accumulators packed in f32x2 along d-pairs.
// ---------------------------------------------------------------------------
__global__ __launch_bounds__(256) void proj_kernel(
    const float* __restrict__ x,
    const float* __restrict__ wq, const float* __restrict__ bq,
    const float* __restrict__ wk, const float* __restrict__ bk,
    const float* __restrict__ wv, const float* __restrict__ bv)
{
    __shared__ __align__(16) float Xs[16][64];      // [c][p]
    __shared__ __align__(16) float Ws[3][16][66];   // [mat][c][d], pad 66 -> conflict-free

    const int n  = blockIdx.z;
    const int d0 = blockIdx.y * 64;
    const int p0 = blockIdx.x * 64;
    const int t  = threadIdx.x;
    const int tx = t & 15;        // p quad
    const int ty = t >> 4;        // d quad

    const float* __restrict__ xn = x + (size_t)n * CP;

    const float* ws[3] = {wq, wk, wv};
    const float* bs[3] = {bq, bk, bv};

    // Accumulators: [mat][d-pair(2)][p(4)], each u64 = {acc[2dp], acc[2dp+1]}
    unsigned long long acc[3][2][4];
    #pragma unroll
    for (int m = 0; m < 3; m++) {
        #pragma unroll
        for (int dp = 0; dp < 2; dp++) {
            float b0 = bs[m][d0 + ty*4 + dp*2 + 0];
            float b1 = bs[m][d0 + ty*4 + dp*2 + 1];
            unsigned long long bp;
            asm("mov.b64 %0,{%1,%2};" : "=l"(bp) : "f"(b0), "f"(b1));
            #pragma unroll
            for (int pc = 0; pc < 4; pc++) acc[m][dp][pc] = bp;
        }
    }

    for (int c0 = 0; c0 < CC; c0 += 16) {
        // Load X tile: 16 rows x 64 p, one float4 per thread, coalesced.
        {
            int c = t >> 4, q4 = t & 15;
            *(float4*)&Xs[c][q4*4] =
                *(const float4*)&xn[(size_t)(c0 + c)*PP + p0 + q4*4];
        }
        // Load W tiles: Ws[m][c][d] = w[(d0+d)*256 + c0 + c]
        #pragma unroll
        for (int m = 0; m < 3; m++) {
            const float* __restrict__ w = ws[m];
            #pragma unroll
            for (int pass = 0; pass < 4; pass++) {
                int c  = t & 15;
                int dd = (t >> 4) + pass*16;
                Ws[m][c][dd] = w[(size_t)(d0 + dd)*CC + c0 + c];
            }
        }
        __syncthreads();

        #pragma unroll
        for (int kk = 0; kk < 16; kk++) {
            float4 xv = *(const float4*)&Xs[kk][tx*4];
            unsigned long long xp[4];
            asm("mov.b64 %0,{%1,%1};" : "=l"(xp[0]) : "f"(xv.x));
            asm("mov.b64 %0,{%1,%1};" : "=l"(xp[1]) : "f"(xv.y));
            asm("mov.b64 %0,{%1,%1};" : "=l"(xp[2]) : "f"(xv.z));
            asm("mov.b64 %0,{%1,%1};" : "=l"(xp[3]) : "f"(xv.w));
            #pragma unroll
            for (int m = 0; m < 3; m++) {
                unsigned long long w0 = *(const unsigned long long*)&Ws[m][kk][ty*4 + 0];
                unsigned long long w1 = *(const unsigned long long*)&Ws[m][kk][ty*4 + 2];
                #pragma unroll
                for (int pc = 0; pc < 4; pc++) {
                    FMA2(acc[m][0][pc], w0, xp[pc]);
                    FMA2(acc[m][1][pc], w1, xp[pc]);
                }
            }
        }
        __syncthreads();
    }

    // Epilogue: unpack and store float4 rows (coalesced).
    float* outs[3] = {g_q, g_k, g_v};
    #pragma unroll
    for (int m = 0; m < 3; m++) {
        float* o = outs[m] + (size_t)n*CP + (size_t)(d0 + ty*4)*PP + p0 + tx*4;
        #pragma unroll
        for (int dp = 0; dp < 2; dp++) {
            float lo[4], hi[4];
            #pragma unroll
            for (int pc = 0; pc < 4; pc++)
                asm("mov.b64 {%0,%1}, %2;" : "=f"(lo[pc]), "=f"(hi[pc]) : "l"(acc[m][dp][pc]));
            *(float4*)(o + (size_t)(dp*2 + 0)*PP) = make_float4(lo[0], lo[1], lo[2], lo[3]);
            *(float4*)(o + (size_t)(dp*2 + 1)*PP) = make_float4(hi[0], hi[1], hi[2], hi[3]);
        }
    }
}

// ---------------------------------------------------------------------------
// Pass 2: per-(b,c) temporal attention + residual epilogue.
// One block per (b,c). q,k staged in dynamic smem (stride 1028 floats keeps
// float4 alignment). S[16][16] by thread-per-(i,j) dot; softmax by 16
// threads; out accumulated in registers streaming v from HBM.
// final[b,c,f,h,w] = gamma * out[b,c,f,hw] + x[b,c,f,h,w]
// ---------------------------------------------------------------------------
#define QS_STRIDE 1028

__global__ __launch_bounds__(256) void attn_kernel(
    const float* __restrict__ x,
    const float* __restrict__ gamma,
    float* __restrict__ out)
{
    extern __shared__ __align__(16) float sm[];
    float* qs = sm;                      // 16 * 1028
    float* ks = sm + 16*QS_STRIDE;       // 16 * 1028
    __shared__ float S[16][16];
    __shared__ float Pm[16][16];

    const int bc = blockIdx.x;
    const int b  = bc >> 8;
    const int c  = bc & 255;
    const int t  = threadIdx.x;

    const size_t qbase = (size_t)(b*16)*CP + (size_t)c*PP;   // g_q[(b*16+f)*CP + c*1024 + p]

    // Stage q,k: 16 frames x 1024 floats, coalesced float4.
    #pragma unroll 1
    for (int f = 0; f < 16; f++) {
        size_t off = qbase + (size_t)f*CP + t*4;
        *(float4*)&qs[f*QS_STRIDE + t*4] = *(const float4*)&g_q[off];
        *(float4*)&ks[f*QS_STRIDE + t*4] = *(const float4*)&g_k[off];
    }
    __syncthreads();

    // Logits: thread t = (i,j)
    {
        const int i = t >> 4, j = t & 15;
        const float* qp = &qs[i*QS_STRIDE];
        const float* kp = &ks[j*QS_STRIDE];
        float s0 = 0.f, s1 = 0.f, s2 = 0.f, s3 = 0.f;
        #pragma unroll 8
        for (int p = 0; p < PP; p += 4) {
            float4 a  = *(const float4*)&qp[p];
            float4 bb = *(const float4*)&kp[p];
            s0 += a.x*bb.x; s1 += a.y*bb.y; s2 += a.z*bb.z; s3 += a.w*bb.w;
        }
        S[i][j] = (s0 + s1) + (s2 + s3);
    }
    __syncthreads();

    // Softmax rows (scale 1/sqrt(256) = 0.0625)
    if (t < 16) {
        float mx = -1e30f;
        float e[16];
        #pragma unroll
        for (int j = 0; j < 16; j++) {
            float v = S[t][j] * 0.0625f;
            e[j] = v;
            mx = fmaxf(mx, v);
        }
        float sum = 0.f;
        #pragma unroll
        for (int j = 0; j < 16; j++) { e[j] = __expf(e[j] - mx); sum += e[j]; }
        float inv = 1.f / sum;
        #pragma unroll
        for (int j = 0; j < 16; j++) Pm[t][j] = e[j] * inv;
    }
    __syncthreads();

    // out[i][p] = sum_j Pm[i][j] * v[j][p]; thread owns p = t + pc*256
    float acc[16][4];
    #pragma unroll
    for (int ii = 0; ii < 16; ii++)
        #pragma unroll
        for (int pc = 0; pc < 4; pc++) acc[ii][pc] = 0.f;

    #pragma unroll 1
    for (int jj = 0; jj < 16; jj++) {
        const float* vp = &g_v[qbase + (size_t)jj*CP];
        float v0 = vp[t + 0*256];
        float v1 = vp[t + 1*256];
        float v2 = vp[t + 2*256];
        float v3 = vp[t + 3*256];
        #pragma unroll
        for (int ii = 0; ii < 16; ii++) {
            float pij = Pm[ii][jj];
            acc[ii][0] += pij * v0;
            acc[ii][1] += pij * v1;
            acc[ii][2] += pij * v2;
            acc[ii][3] += pij * v3;
        }
    }

    // Epilogue: gamma*out + x in x layout
    const float g = gamma[0];
    const size_t xbase = (size_t)b*CFP + (size_t)c*(FF*PP);
    #pragma unroll
    for (int ii = 0; ii < 16; ii++) {
        #pragma unroll
        for (int pc = 0; pc < 4; pc++) {
            size_t idx = xbase + (size_t)ii*PP + t + pc*256;
            out[idx] = g * acc[ii][pc] + x[idx];
        }
    }
}

// ---------------------------------------------------------------------------
extern "C" void kernel_launch(void* const* d_in, const int* in_sizes, int n_in,
                              void* d_out, int out_size)
{
    const float* x     = (const float*)d_in[0];
    const float* wq    = (const float*)d_in[1];
    const float* bq    = (const float*)d_in[2];
    const float* wk    = (const float*)d_in[3];
    const float* bk    = (const float*)d_in[4];
    const float* wv    = (const float*)d_in[5];
    const float* bv    = (const float*)d_in[6];
    const float* gamma = (const float*)d_in[7];
    float* out = (float*)d_out;

    // Pass 1: projections
    dim3 g1(PP/64, CC/64, NN);   // (16, 4, 64)
    proj_kernel<<<g1, 256>>>(x, wq, bq, wk, bk, wv, bv);

    // Pass 2: attention
    size_t smem2 = (size_t)2 * 16 * QS_STRIDE * sizeof(float);  // 131584 B
    static int smem_set = 0;
    if (!smem_set) {
        cudaFuncSetAttribute(attn_kernel,
                             cudaFuncAttributeMaxDynamicSharedMemorySize,
                             (int)smem2);
        smem_set = 1;
    }
    attn_kernel<<<BB*CC, 256, smem2>>>(x, gamma, out);
}

// round 8
// speedup vs baseline: 1.0732x; 1.0732x over previous
#include <cuda_runtime.h>
#include <cuda_fp16.h>
#include <cstdint>

// Problem constants
#define BB 4
#define CC 256
#define FF 16
#define PP 1024                 // H*W
#define NN 64                   // B*F
#define CP (CC*PP)              // 262144
#define CFP (CC*FF*PP)          // 4194304

// Scratch (allocation-guard-safe static device arrays)
__device__ float g_q[(size_t)NN*CP];
__device__ float g_k[(size_t)NN*CP];
__device__ float g_v[(size_t)NN*CP];
__device__ float g_canary[(size_t)16*CP];       // canary output, never read
__device__ __half g_whi[3*CC*CC];               // zeros; canary input
__device__ __half g_wlo[3*CC*CC];               // zeros; canary input

#define FMA2(acc, a, b) asm("fma.rn.f32x2 %0, %1, %2, %3;" : "=l"(acc) : "l"(a), "l"(b), "l"(acc))

__device__ __forceinline__ uint32_t smem_u32(const void* p) {
    uint32_t a;
    asm("{ .reg .u64 t; cvta.to.shared.u64 t, %1; cvt.u32.u64 %0, t; }" : "=r"(a) : "l"(p));
    return a;
}

#define MMA16816(C, A, B)                                                     \
    asm volatile("mma.sync.aligned.m16n8k16.row.col.f32.f16.f16.f32 "         \
                 "{%0,%1,%2,%3}, {%4,%5,%6,%7}, {%8,%9}, {%0,%1,%2,%3};"      \
                 : "+f"((C)[0]), "+f"((C)[1]), "+f"((C)[2]), "+f"((C)[3])     \
                 : "r"((A)[0]), "r"((A)[1]), "r"((A)[2]), "r"((A)[3]),        \
                   "r"((B)[0]), "r"((B)[1]))

#define LDMX4(R, ADDR)                                                        \
    asm volatile("ldmatrix.sync.aligned.m8n8.x4.shared.b16 {%0,%1,%2,%3}, [%4];" \
                 : "=r"((R)[0]), "=r"((R)[1]), "=r"((R)[2]), "=r"((R)[3])     \
                 : "r"(ADDR))

#define LDMX2(R, ADDR)                                                        \
    asm volatile("ldmatrix.sync.aligned.m8n8.x2.shared.b16 {%0,%1}, [%2];"    \
                 : "=r"((R)[0]), "=r"((R)[1]) : "r"(ADDR))

// ---------------------------------------------------------------------------
// Kernel 1: fused QKV projection GEMM — EXACT copy of the Round-1 kernel
// that passed at rel_err 6.8e-9 (fp32, f32x2-packed FMAs).
// ---------------------------------------------------------------------------
__global__ __launch_bounds__(256) void r8_proj(
    const float* __restrict__ x,
    const float* __restrict__ wq, const float* __restrict__ bq,
    const float* __restrict__ wk, const float* __restrict__ bk,
    const float* __restrict__ wv, const float* __restrict__ bv)
{
    __shared__ __align__(16) float Xs[16][64];      // [c][p]
    __shared__ __align__(16) float Ws[3][16][66];   // [mat][c][d]

    const int n  = blockIdx.z;
    const int d0 = blockIdx.y * 64;
    const int p0 = blockIdx.x * 64;
    const int t  = threadIdx.x;
    const int tx = t & 15;        // p quad
    const int ty = t >> 4;        // d quad

    const float* __restrict__ xn = x + (size_t)n * CP;

    const float* ws[3] = {wq, wk, wv};
    const float* bs[3] = {bq, bk, bv};

    unsigned long long acc[3][2][4];
    #pragma unroll
    for (int m = 0; m < 3; m++) {
        #pragma unroll
        for (int dp = 0; dp < 2; dp++) {
            float b0 = bs[m][d0 + ty*4 + dp*2 + 0];
            float b1 = bs[m][d0 + ty*4 + dp*2 + 1];
            unsigned long long bp;
            asm("mov.b64 %0,{%1,%2};" : "=l"(bp) : "f"(b0), "f"(b1));
            #pragma unroll
            for (int pc = 0; pc < 4; pc++) acc[m][dp][pc] = bp;
        }
    }

    for (int c0 = 0; c0 < CC; c0 += 16) {
        {
            int c = t >> 4, q4 = t & 15;
            *(float4*)&Xs[c][q4*4] =
                *(const float4*)&xn[(size_t)(c0 + c)*PP + p0 + q4*4];
        }
        #pragma unroll
        for (int m = 0; m < 3; m++) {
            const float* __restrict__ w = ws[m];
            #pragma unroll
            for (int pass = 0; pass < 4; pass++) {
                int c  = t & 15;
                int dd = (t >> 4) + pass*16;
                Ws[m][c][dd] = w[(size_t)(d0 + dd)*CC + c0 + c];
            }
        }
        __syncthreads();

        #pragma unroll
        for (int kk = 0; kk < 16; kk++) {
            float4 xv = *(const float4*)&Xs[kk][tx*4];
            unsigned long long xp[4];
            asm("mov.b64 %0,{%1,%1};" : "=l"(xp[0]) : "f"(xv.x));
            asm("mov.b64 %0,{%1,%1};" : "=l"(xp[1]) : "f"(xv.y));
            asm("mov.b64 %0,{%1,%1};" : "=l"(xp[2]) : "f"(xv.z));
            asm("mov.b64 %0,{%1,%1};" : "=l"(xp[3]) : "f"(xv.w));
            #pragma unroll
            for (int m = 0; m < 3; m++) {
                unsigned long long w0 = *(const unsigned long long*)&Ws[m][kk][ty*4 + 0];
                unsigned long long w1 = *(const unsigned long long*)&Ws[m][kk][ty*4 + 2];
                #pragma unroll
                for (int pc = 0; pc < 4; pc++) {
                    FMA2(acc[m][0][pc], w0, xp[pc]);
                    FMA2(acc[m][1][pc], w1, xp[pc]);
                }
            }
        }
        __syncthreads();
    }

    float* outs[3] = {g_q, g_k, g_v};
    #pragma unroll
    for (int m = 0; m < 3; m++) {
        float* o = outs[m] + (size_t)n*CP + (size_t)(d0 + ty*4)*PP + p0 + tx*4;
        #pragma unroll
        for (int dp = 0; dp < 2; dp++) {
            float lo[4], hi[4];
            #pragma unroll
            for (int pc = 0; pc < 4; pc++)
                asm("mov.b64 {%0,%1}, %2;" : "=f"(lo[pc]), "=f"(hi[pc]) : "l"(acc[m][dp][pc]));
            *(float4*)(o + (size_t)(dp*2 + 0)*PP) = make_float4(lo[0], lo[1], lo[2], lo[3]);
            *(float4*)(o + (size_t)(dp*2 + 1)*PP) = make_float4(hi[0], hi[1], hi[2], hi[3]);
        }
    }
}

// ---------------------------------------------------------------------------
// Kernel 2: per-(b,c) temporal attention, chunked q/k staging (36 KB smem,
// 2 CTAs/SM). Stride 264 floats -> conflict-free k-row reads.
// ---------------------------------------------------------------------------
#define QS 264

__global__ __launch_bounds__(256, 2) void r8_attn(
    const float* __restrict__ x,
    const float* __restrict__ gamma,
    float* __restrict__ out)
{
    __shared__ float qs[16][QS];
    __shared__ float ks[16][QS];
    __shared__ float S[16][17];
    __shared__ float Pm[16][16];

    const int bc = blockIdx.x;
    const int b  = bc >> 8;
    const int c  = bc & 255;
    const int t  = threadIdx.x;

    const size_t qbase = (size_t)(b * 16) * CP + (size_t)c * PP;

    // ---- logits: accumulate S over 4 chunks of 256 p
    const int i = t >> 4, j = t & 15;
    float s0 = 0.f, s1 = 0.f, s2 = 0.f, s3 = 0.f;
    #pragma unroll 1
    for (int ch = 0; ch < 4; ch++) {
        __syncthreads();
        {
            int fr = t >> 4, q0 = t & 15;
            size_t base = qbase + (size_t)fr * CP + ch * 256;
            #pragma unroll
            for (int u = 0; u < 4; u++) {
                *(float4*)&qs[fr][(q0 + u * 16) * 4] = *(const float4*)&g_q[base + (q0 + u * 16) * 4];
                *(float4*)&ks[fr][(q0 + u * 16) * 4] = *(const float4*)&g_k[base + (q0 + u * 16) * 4];
            }
        }
        __syncthreads();
        const float* qp = &qs[i][0];
        const float* kp = &ks[j][0];
        #pragma unroll 8
        for (int p = 0; p < 256; p += 4) {
            float4 a = *(const float4*)&qp[p];
            float4 bb = *(const float4*)&kp[p];
            s0 += a.x * bb.x; s1 += a.y * bb.y; s2 += a.z * bb.z; s3 += a.w * bb.w;
        }
    }
    S[i][j] = (s0 + s1) + (s2 + s3);
    __syncthreads();

    // ---- softmax rows (scale 1/sqrt(256))
    if (t < 16) {
        float mx = -1e30f;
        float e[16];
        #pragma unroll
        for (int jj = 0; jj < 16; jj++) {
            float v = S[t][jj] * 0.0625f;
            e[jj] = v;
            mx = fmaxf(mx, v);
        }
        float sum = 0.f;
        #pragma unroll
        for (int jj = 0; jj < 16; jj++) { e[jj] = __expf(e[jj] - mx); sum += e[jj]; }
        float inv = 1.f / sum;
        #pragma unroll
        for (int jj = 0; jj < 16; jj++) Pm[t][jj] = e[jj] * inv;
    }
    __syncthreads();

    // ---- out[i][p] = sum_j Pm[i][j] * v[j][p]; thread owns p = t + pc*256
    float acc[16][4];
    #pragma unroll
    for (int ii = 0; ii < 16; ii++)
        #pragma unroll
        for (int pc = 0; pc < 4; pc++) acc[ii][pc] = 0.f;

    #pragma unroll 1
    for (int jj = 0; jj < 16; jj++) {
        const float* vp = &g_v[qbase + (size_t)jj * CP];
        float v0 = vp[t + 0 * 256];
        float v1 = vp[t + 1 * 256];
        float v2 = vp[t + 2 * 256];
        float v3 = vp[t + 3 * 256];
        #pragma unroll
        for (int ii = 0; ii < 16; ii++) {
            float pij = Pm[ii][jj];
            acc[ii][0] += pij * v0;
            acc[ii][1] += pij * v1;
            acc[ii][2] += pij * v2;
            acc[ii][3] += pij * v3;
        }
    }

    // ---- epilogue: gamma*out + x
    const float g = gamma[0];
    const size_t xbase = (size_t)b * CFP + (size_t)c * (FF * PP);
    #pragma unroll
    for (int ii = 0; ii < 16; ii++) {
        #pragma unroll
        for (int pc = 0; pc < 4; pc++) {
            size_t idx = xbase + (size_t)ii * PP + t + pc * 256;
            out[idx] = g * acc[ii][pc] + x[idx];
        }
    }
}

// ---------------------------------------------------------------------------
// Kernel 3: CANARY — HMMA kernel in the exact style of the failed rounds
// (dynamic smem 83968 + attribute, mma.sync + ldmatrix). Writes ONLY to
// g_canary (never read). Its execution (or silent absence) is visible in
// dur_us; it cannot affect correctness.
// ---------------------------------------------------------------------------
#define TILE_H 5120
#define CANARY_SMEM 83968

__global__ __launch_bounds__(256, 1) void r8_canary(const float* __restrict__ x)
{
    extern __shared__ __align__(16) __half sh[];
    __half* As = sh;
    __half* Bs = sh + 4 * TILE_H;

    const int p0 = blockIdx.x * 128;      // 0..7
    const int m  = blockIdx.y;            // 0..2
    const int n  = blockIdx.z;            // 0..15
    const int t  = threadIdx.x;
    const int lane = t & 31;
    const int wid  = t >> 5;
    const int wm   = wid & 1;
    const int wn   = wid >> 1;

    const __half* __restrict__ whp = g_whi + (size_t)m * 65536;
    const __half* __restrict__ wlp = g_wlo + (size_t)m * 65536;
    const float*  __restrict__ xn  = x + (size_t)n * CP;

    float chi[4][4][4], clo[4][4][4];
    #pragma unroll
    for (int mi = 0; mi < 4; mi++)
        #pragma unroll
        for (int ni = 0; ni < 4; ni++)
            #pragma unroll
            for (int r = 0; r < 4; r++) { chi[mi][ni][r] = 0.f; clo[mi][ni][r] = 0.f; }

    const int arow = t >> 1;
    const int acol = (t & 1) * 16;
    const int bp   = t & 127;
    const int bc0  = t >> 7;

    #pragma unroll 1
    for (int kc = 0; kc < 8; kc++) {
        // load + convert (single-buffered canary: simpler, still exercises path)
        {
            size_t wo = (size_t)arow*256 + kc*32 + acol;
            uint4 rah0 = *(const uint4*)(whp + wo);
            uint4 ral0 = *(const uint4*)(wlp + wo);
            __half* ah = As; __half* al = ah + TILE_H;
            *(uint4*)&ah[arow*40 + acol] = rah0;
            *(uint4*)&al[arow*40 + acol] = ral0;
            #pragma unroll
            for (int i2 = 0; i2 < 8; i2++) {
                int c2 = i2*2 + bc0;
                const float* xp = xn + (size_t)(kc*32 + c2*2)*PP + p0 + bp;
                __half2 hh = __floats2half2_rn(xp[0], xp[PP]);
                __half* bh = Bs;
                *(uint32_t*)&bh[bp*40 + c2*2] = *(uint32_t*)&hh;
            }
        }
        __syncthreads();

        const uint32_t ah_s = smem_u32(As);
        const uint32_t al_s = ah_s + TILE_H*2;
        const uint32_t bh_s = smem_u32(Bs);
        #pragma unroll
        for (int ks = 0; ks < 2; ks++) {
            const uint32_t a_off = (uint32_t)((wm*64 + (lane & 15))*40 + ks*16 + (lane >> 4)*8) * 2;
            const uint32_t b_off = (uint32_t)((wn*32 + (lane & 7))*40 + ks*16 + ((lane >> 3) & 1)*8) * 2;
            uint32_t afh[4][4], afl[4][4], bfh[4][2];
            #pragma unroll
            for (int mi = 0; mi < 4; mi++) {
                LDMX4(afh[mi], ah_s + a_off + (uint32_t)(mi*16*40)*2);
                LDMX4(afl[mi], al_s + a_off + (uint32_t)(mi*16*40)*2);
            }
            #pragma unroll
            for (int ni = 0; ni < 4; ni++)
                LDMX2(bfh[ni], bh_s + b_off + (uint32_t)(ni*8*40)*2);
            #pragma unroll
            for (int mi = 0; mi < 4; mi++)
                #pragma unroll
                for (int ni = 0; ni < 4; ni++) {
                    MMA16816(chi[mi][ni], afh[mi], bfh[ni]);
                    MMA16816(clo[mi][ni], afl[mi], bfh[ni]);
                    MMA16816(clo[mi][ni], afh[mi], bfh[ni]);
                }
        }
        __syncthreads();
    }

    const int gid = lane >> 2, tid4 = lane & 3;
    #pragma unroll
    for (int mi = 0; mi < 4; mi++) {
        int d_r = wm*64 + mi*16 + gid;
        float* o0 = g_canary + (size_t)n*CP + (size_t)d_r*PP + p0 + wn*32 + tid4*2;
        float* o1 = o0 + (size_t)8*PP;
        #pragma unroll
        for (int ni = 0; ni < 4; ni++) {
            *(float2*)(o0 + ni*8) = make_float2(chi[mi][ni][0] + clo[mi][ni][0], chi[mi][ni][1] + clo[mi][ni][1]);
            *(float2*)(o1 + ni*8) = make_float2(chi[mi][ni][2] + clo[mi][ni][2], chi[mi][ni][3] + clo[mi][ni][3]);
        }
    }
}

// ---------------------------------------------------------------------------
extern "C" void kernel_launch(void* const* d_in, const int* in_sizes, int n_in,
                              void* d_out, int out_size)
{
    const float* x     = (const float*)d_in[0];
    const float* wq    = (const float*)d_in[1];
    const float* bq    = (const float*)d_in[2];
    const float* wk    = (const float*)d_in[3];
    const float* bk    = (const float*)d_in[4];
    const float* wv    = (const float*)d_in[5];
    const float* bv    = (const float*)d_in[6];
    const float* gamma = (const float*)d_in[7];
    float* out = (float*)d_out;

    // Pass 1: projections (proven R1 kernel)
    r8_proj<<<dim3(PP/64, CC/64, NN), 256>>>(x, wq, bq, wk, bk, wv, bv);

    // Pass 2: attention (chunked, higher occupancy)
    r8_attn<<<BB*CC, 256>>>(x, gamma, out);

    // Canary: HMMA-style kernel with dynamic smem; output unused.
    cudaFuncSetAttribute(r8_canary,
                         cudaFuncAttributeMaxDynamicSharedMemorySize, CANARY_SMEM);
    r8_canary<<<dim3(8, 3, 16), 256, CANARY_SMEM>>>(x);
}

// round 10
// speedup vs baseline: 1.6415x; 1.5295x over previous
#include <cuda_runtime.h>
#include <cuda_fp16.h>
#include <cstdint>

// Problem constants
#define BB 4
#define CC 256
#define FF 16
#define PP 1024                 // H*W
#define NN 64                   // B*F
#define CP (CC*PP)              // 262144
#define CFP (CC*FF*PP)          // 4194304

#define LO_SCALE   2048.0f
#define LO_INV     (1.0f/2048.0f)

// Scratch (allocation-guard-safe static device arrays)
__device__ float g_q[(size_t)NN*CP];
__device__ float g_k[(size_t)NN*CP];
__device__ float g_v[(size_t)NN*CP];
__device__ __half g_whi[3*CC*CC];
__device__ __half g_wlo[3*CC*CC];   // (w - trunc11(w)) * 2048

__device__ __forceinline__ uint32_t smem_u32(const void* p) {
    uint32_t a;
    asm("{ .reg .u64 t; cvta.to.shared.u64 t, %1; cvt.u32.u64 %0, t; }" : "=r"(a) : "l"(p));
    return a;
}

// Split v into fp16-exact hi (mantissa truncated via integer masking) and
// scaled fp16 lo residual.
__device__ __forceinline__ void split_hi_lo(float v, __half& h, __half& l) {
    uint32_t bi = __float_as_uint(v);
    float hf = __uint_as_float(bi & 0xFFFFE000u);   // top 10 explicit mantissa bits
    h = __float2half_rn(hf);                        // exact in normal range
    l = __float2half_rn((v - hf) * LO_SCALE);
}

#define MMA16816(C, A, B)                                                     \
    asm volatile("mma.sync.aligned.m16n8k16.row.col.f32.f16.f16.f32 "         \
                 "{%0,%1,%2,%3}, {%4,%5,%6,%7}, {%8,%9}, {%0,%1,%2,%3};"      \
                 : "+f"((C)[0]), "+f"((C)[1]), "+f"((C)[2]), "+f"((C)[3])     \
                 : "r"((A)[0]), "r"((A)[1]), "r"((A)[2]), "r"((A)[3]),        \
                   "r"((B)[0]), "r"((B)[1]))

#define LDMX4(R, ADDR)                                                        \
    asm volatile("ldmatrix.sync.aligned.m8n8.x4.shared.b16 {%0,%1,%2,%3}, [%4];" \
                 : "=r"((R)[0]), "=r"((R)[1]), "=r"((R)[2]), "=r"((R)[3])     \
                 : "r"(ADDR))

#define LDMX2(R, ADDR)                                                        \
    asm volatile("ldmatrix.sync.aligned.m8n8.x2.shared.b16 {%0,%1}, [%2];"    \
                 : "=r"((R)[0]), "=r"((R)[1]) : "r"(ADDR))

// ---------------------------------------------------------------------------
// Kernel 0: split weights fp32 -> fp16 hi + scaled lo residual
// ---------------------------------------------------------------------------
__global__ __launch_bounds__(512) void r10_wsplit(
    const float* __restrict__ wq, const float* __restrict__ wk, const float* __restrict__ wv)
{
    int idx = blockIdx.x * 512 + threadIdx.x;          // [0, 3*65536)
    const float* src = (idx < 65536) ? wq : (idx < 131072 ? wk : wv);
    float v = src[idx & 65535];
    __half h, l;
    split_hi_lo(v, h, l);
    g_whi[idx] = h;
    g_wlo[idx] = l;
}

// ---------------------------------------------------------------------------
// Kernel 1: QKV projection GEMM, mma.sync m16n8k16, scaled 3-term split:
//   W.X = Wh.Xh + (Wl.Xh + Wh.Xl) * 2^-11   (+O(2^-20), dropped)
// Grid: (pt, m*2+dh, n) = (8, 6, 64).  CTA computes C[128d x 128p] for
// matrix m = y>>1, d-half d0 = (y&1)*128  <-- FIX: full d=256 now covered.
// K=256 in 8 chunks of 32, double-buffered.
// ---------------------------------------------------------------------------
#define TILE_H 5120   // halves per tile (128*40)
#define PROJ_SMEM 81920

__global__ __launch_bounds__(256, 1) void r10_proj(
    const float* __restrict__ x,
    const float* __restrict__ bq,
    const float* __restrict__ bk,
    const float* __restrict__ bv)
{
    extern __shared__ __align__(16) __half sh[];
    __half* As = sh;               // [buf][hl][TILE_H]
    __half* Bs = sh + 4 * TILE_H;  // [buf][hl][TILE_H]

    const int p0 = blockIdx.x * 128;        // 0..7  (p tile)
    const int m  = blockIdx.y >> 1;         // 0..2  (q,k,v)
    const int d0 = (blockIdx.y & 1) * 128;  // 0 or 128  (d half)
    const int n  = blockIdx.z;              // 0..63
    const int t  = threadIdx.x;
    const int lane = t & 31;
    const int wid  = t >> 5;
    const int wm   = wid & 1;               // 0..1 (64 d each within the 128 block)
    const int wn   = wid >> 1;              // 0..3 (32 p each)

    const __half* __restrict__ whp = g_whi + (size_t)m * 65536;
    const __half* __restrict__ wlp = g_wlo + (size_t)m * 65536;
    const float*  __restrict__ xn  = x + (size_t)n * CP;

    float chi[4][4][4], clo[4][4][4];
    #pragma unroll
    for (int mi = 0; mi < 4; mi++)
        #pragma unroll
        for (int ni = 0; ni < 4; ni++)
            #pragma unroll
            for (int r = 0; r < 4; r++) { chi[mi][ni][r] = 0.f; clo[mi][ni][r] = 0.f; }

    const int arow = t >> 1;              // 0..127 (d row within block)
    const int acol = (t & 1) * 16;        // half offset within 32-wide K chunk
    const int bp   = t & 127;             // p row
    const int bc0  = t >> 7;              // 0..1

    uint4 rah0, rah1, ral0, ral1;
    uint32_t rbh[8], rbl[8];

    #define TA_LDG(kc)                                                          \
        do {                                                                    \
            size_t wo = (size_t)(d0 + arow)*256 + (kc)*32 + acol;               \
            rah0 = *(const uint4*)(whp + wo);                                   \
            rah1 = *(const uint4*)(whp + wo + 8);                               \
            ral0 = *(const uint4*)(wlp + wo);                                   \
            ral1 = *(const uint4*)(wlp + wo + 8);                               \
            _Pragma("unroll")                                                   \
            for (int i = 0; i < 8; i++) {                                       \
                int c2 = i*2 + bc0;                                             \
                const float* xp = xn + (size_t)((kc)*32 + c2*2)*PP + p0 + bp;   \
                float v0 = xp[0], v1 = xp[PP];                                  \
                __half h0, l0, h1, l1;                                          \
                split_hi_lo(v0, h0, l0);                                        \
                split_hi_lo(v1, h1, l1);                                        \
                __half2 hh = __halves2half2(h0, h1);                            \
                __half2 ll = __halves2half2(l0, l1);                            \
                rbh[i] = *(uint32_t*)&hh;                                       \
                rbl[i] = *(uint32_t*)&ll;                                       \
            }                                                                   \
        } while (0)

    #define TA_STS(buf)                                                         \
        do {                                                                    \
            __half* ah = As + (buf)*2*TILE_H;                                   \
            __half* al = ah + TILE_H;                                           \
            *(uint4*)&ah[arow*40 + acol]     = rah0;                            \
            *(uint4*)&ah[arow*40 + acol + 8] = rah1;                            \
            *(uint4*)&al[arow*40 + acol]     = ral0;                            \
            *(uint4*)&al[arow*40 + acol + 8] = ral1;                            \
            __half* bh = Bs + (buf)*2*TILE_H;                                   \
            __half* bl = bh + TILE_H;                                           \
            _Pragma("unroll")                                                   \
            for (int i = 0; i < 8; i++) {                                       \
                int c2 = i*2 + bc0;                                             \
                *(uint32_t*)&bh[bp*40 + c2*2] = rbh[i];                         \
                *(uint32_t*)&bl[bp*40 + c2*2] = rbl[i];                         \
            }                                                                   \
        } while (0)

    TA_LDG(0);
    TA_STS(0);
    __syncthreads();

    #pragma unroll 1
    for (int kc = 0; kc < 8; kc++) {
        if (kc < 7) TA_LDG(kc + 1);

        const uint32_t ah_s = smem_u32(As + (kc & 1)*2*TILE_H);
        const uint32_t al_s = ah_s + TILE_H*2;
        const uint32_t bh_s = smem_u32(Bs + (kc & 1)*2*TILE_H);
        const uint32_t bl_s = bh_s + TILE_H*2;

        #pragma unroll
        for (int ks = 0; ks < 2; ks++) {
            const uint32_t a_off = (uint32_t)((wm*64 + (lane & 15))*40 + ks*16 + (lane >> 4)*8) * 2;
            const uint32_t b_off = (uint32_t)((wn*32 + (lane & 7))*40 + ks*16 + ((lane >> 3) & 1)*8) * 2;

            uint32_t afh[4][4], afl[4][4], bfh[4][2], bfl[4][2];
            #pragma unroll
            for (int mi = 0; mi < 4; mi++) {
                LDMX4(afh[mi], ah_s + a_off + (uint32_t)(mi*16*40)*2);
                LDMX4(afl[mi], al_s + a_off + (uint32_t)(mi*16*40)*2);
            }
            #pragma unroll
            for (int ni = 0; ni < 4; ni++) {
                LDMX2(bfh[ni], bh_s + b_off + (uint32_t)(ni*8*40)*2);
                LDMX2(bfl[ni], bl_s + b_off + (uint32_t)(ni*8*40)*2);
            }
            #pragma unroll
            for (int mi = 0; mi < 4; mi++)
                #pragma unroll
                for (int ni = 0; ni < 4; ni++) {
                    MMA16816(chi[mi][ni], afh[mi], bfh[ni]);
                    MMA16816(clo[mi][ni], afl[mi], bfh[ni]);
                    MMA16816(clo[mi][ni], afh[mi], bfl[ni]);
                }
        }

        if (kc < 7) TA_STS((kc + 1) & 1);
        __syncthreads();
    }

    // ---- epilogue: combine hi + lo*2^-11, add bias, store fp32
    const float* __restrict__ bias = (m == 0) ? bq : (m == 1) ? bk : bv;
    float* __restrict__ ob = (m == 0) ? g_q : (m == 1) ? g_k : g_v;
    const int gid = lane >> 2, tid4 = lane & 3;
    const int col = p0 + wn*32 + tid4*2;

    #pragma unroll
    for (int mi = 0; mi < 4; mi++) {
        int d_r = d0 + wm*64 + mi*16 + gid;
        float b0 = bias[d_r];
        float b1 = bias[d_r + 8];
        float* o0 = ob + (size_t)n*CP + (size_t)d_r*PP + col;
        float* o1 = o0 + (size_t)8*PP;
        #pragma unroll
        for (int ni = 0; ni < 4; ni++) {
            float r0 = fmaf(clo[mi][ni][0], LO_INV, chi[mi][ni][0]) + b0;
            float r1 = fmaf(clo[mi][ni][1], LO_INV, chi[mi][ni][1]) + b0;
            float r2 = fmaf(clo[mi][ni][2], LO_INV, chi[mi][ni][2]) + b1;
            float r3 = fmaf(clo[mi][ni][3], LO_INV, chi[mi][ni][3]) + b1;
            *(float2*)(o0 + ni*8) = make_float2(r0, r1);
            *(float2*)(o1 + ni*8) = make_float2(r2, r3);
        }
    }
    #undef TA_LDG
    #undef TA_STS
}

// ---------------------------------------------------------------------------
// Kernel 2: per-(b,c) temporal attention, chunked q/k staging (36 KB static
// smem, 2 CTAs/SM).
// ---------------------------------------------------------------------------
#define QS 264

__global__ __launch_bounds__(256, 2) void r10_attn(
    const float* __restrict__ x,
    const float* __restrict__ gamma,
    float* __restrict__ out)
{
    __shared__ float qs[16][QS];
    __shared__ float ks[16][QS];
    __shared__ float S[16][17];
    __shared__ float Pm[16][16];

    const int bc = blockIdx.x;
    const int b  = bc >> 8;
    const int c  = bc & 255;
    const int t  = threadIdx.x;

    const size_t qbase = (size_t)(b * 16) * CP + (size_t)c * PP;

    const int i = t >> 4, j = t & 15;
    float s0 = 0.f, s1 = 0.f, s2 = 0.f, s3 = 0.f;
    #pragma unroll 1
    for (int ch = 0; ch < 4; ch++) {
        __syncthreads();
        {
            int fr = t >> 4, q0 = t & 15;
            size_t base = qbase + (size_t)fr * CP + ch * 256;
            #pragma unroll
            for (int u = 0; u < 4; u++) {
                *(float4*)&qs[fr][(q0 + u * 16) * 4] = *(const float4*)&g_q[base + (q0 + u * 16) * 4];
                *(float4*)&ks[fr][(q0 + u * 16) * 4] = *(const float4*)&g_k[base + (q0 + u * 16) * 4];
            }
        }
        __syncthreads();
        const float* qp = &qs[i][0];
        const float* kp = &ks[j][0];
        #pragma unroll 8
        for (int p = 0; p < 256; p += 4) {
            float4 a = *(const float4*)&qp[p];
            float4 bb = *(const float4*)&kp[p];
            s0 += a.x * bb.x; s1 += a.y * bb.y; s2 += a.z * bb.z; s3 += a.w * bb.w;
        }
    }
    S[i][j] = (s0 + s1) + (s2 + s3);
    __syncthreads();

    if (t < 16) {
        float mx = -1e30f;
        float e[16];
        #pragma unroll
        for (int jj = 0; jj < 16; jj++) {
            float v = S[t][jj] * 0.0625f;
            e[jj] = v;
            mx = fmaxf(mx, v);
        }
        float sum = 0.f;
        #pragma unroll
        for (int jj = 0; jj < 16; jj++) { e[jj] = __expf(e[jj] - mx); sum += e[jj]; }
        float inv = 1.f / sum;
        #pragma unroll
        for (int jj = 0; jj < 16; jj++) Pm[t][jj] = e[jj] * inv;
    }
    __syncthreads();

    float acc[16][4];
    #pragma unroll
    for (int ii = 0; ii < 16; ii++)
        #pragma unroll
        for (int pc = 0; pc < 4; pc++) acc[ii][pc] = 0.f;

    #pragma unroll 1
    for (int jj = 0; jj < 16; jj++) {
        const float* vp = &g_v[qbase + (size_t)jj * CP];
        float v0 = vp[t + 0 * 256];
        float v1 = vp[t + 1 * 256];
        float v2 = vp[t + 2 * 256];
        float v3 = vp[t + 3 * 256];
        #pragma unroll
        for (int ii = 0; ii < 16; ii++) {
            float pij = Pm[ii][jj];
            acc[ii][0] += pij * v0;
            acc[ii][1] += pij * v1;
            acc[ii][2] += pij * v2;
            acc[ii][3] += pij * v3;
        }
    }

    const float g = gamma[0];
    const size_t xbase = (size_t)b * CFP + (size_t)c * (FF * PP);
    #pragma unroll
    for (int ii = 0; ii < 16; ii++) {
        #pragma unroll
        for (int pc = 0; pc < 4; pc++) {
            size_t idx = xbase + (size_t)ii * PP + t + pc * 256;
            out[idx] = g * acc[ii][pc] + x[idx];
        }
    }
}

// ---------------------------------------------------------------------------
extern "C" void kernel_launch(void* const* d_in, const int* in_sizes, int n_in,
                              void* d_out, int out_size)
{
    const float* x     = (const float*)d_in[0];
    const float* wq    = (const float*)d_in[1];
    const float* bq    = (const float*)d_in[2];
    const float* wk    = (const float*)d_in[3];
    const float* bk    = (const float*)d_in[4];
    const float* wv    = (const float*)d_in[5];
    const float* bv    = (const float*)d_in[6];
    const float* gamma = (const float*)d_in[7];
    float* out = (float*)d_out;

    cudaFuncSetAttribute(r10_proj,
                         cudaFuncAttributeMaxDynamicSharedMemorySize, PROJ_SMEM);

    r10_wsplit<<<384, 512>>>(wq, wk, wv);
    r10_proj<<<dim3(8, 6, 64), 256, PROJ_SMEM>>>(x, bq, bk, bv);
    r10_attn<<<BB*CC, 256>>>(x, gamma, out);
}

// round 13
// speedup vs baseline: 1.7884x; 1.0895x over previous
#include <cuda_runtime.h>
#include <cuda_fp16.h>
#include <cstdint>

// Problem constants
#define BB 4
#define CC 256
#define FF 16
#define PP 1024                 // H*W
#define NN 64                   // B*F
#define CP (CC*PP)              // 262144
#define CFP (CC*FF*PP)          // 4194304

#define LO_SCALE   2048.0f
#define LO_INV     (1.0f/2048.0f)

// Scratch (allocation-guard-safe static device arrays).
// __align__(16): accessed as uint4.
__device__ __align__(16) float g_q[(size_t)NN*CP];
__device__ __align__(16) float g_k[(size_t)NN*CP];
__device__ __align__(16) float g_v[(size_t)NN*CP];
__device__ __align__(16) __half g_whi[3*CC*CC];
__device__ __align__(16) __half g_wlo[3*CC*CC];
__device__ __align__(16) __half g_xthi[(size_t)NN*PP*CC];   // x hi, transposed [n][p][c]
__device__ __align__(16) __half g_xtlo[(size_t)NN*PP*CC];   // x lo (x2048), transposed

__device__ __forceinline__ uint32_t smem_u32(const void* p) {
    uint32_t a;
    asm("{ .reg .u64 t; cvta.to.shared.u64 t, %1; cvt.u32.u64 %0, t; }" : "=r"(a) : "l"(p));
    return a;
}

// Split v into fp16-exact hi (mantissa truncated via integer masking) and
// scaled fp16 lo residual.
__device__ __forceinline__ void split_hi_lo(float v, __half& h, __half& l) {
    uint32_t bi = __float_as_uint(v);
    float hf = __uint_as_float(bi & 0xFFFFE000u);   // top 10 explicit mantissa bits
    h = __float2half_rn(hf);                        // exact in normal range
    l = __float2half_rn((v - hf) * LO_SCALE);
}

#define MMA16816(C, A, B)                                                     \
    asm volatile("mma.sync.aligned.m16n8k16.row.col.f32.f16.f16.f32 "         \
                 "{%0,%1,%2,%3}, {%4,%5,%6,%7}, {%8,%9}, {%0,%1,%2,%3};"      \
                 : "+f"((C)[0]), "+f"((C)[1]), "+f"((C)[2]), "+f"((C)[3])     \
                 : "r"((A)[0]), "r"((A)[1]), "r"((A)[2]), "r"((A)[3]),        \
                   "r"((B)[0]), "r"((B)[1]))

#define LDMX4(R, ADDR)                                                        \
    asm volatile("ldmatrix.sync.aligned.m8n8.x4.shared.b16 {%0,%1,%2,%3}, [%4];" \
                 : "=r"((R)[0]), "=r"((R)[1]), "=r"((R)[2]), "=r"((R)[3])     \
                 : "r"(ADDR))

#define LDMX2(R, ADDR)                                                        \
    asm volatile("ldmatrix.sync.aligned.m8n8.x2.shared.b16 {%0,%1}, [%2];"    \
                 : "=r"((R)[0]), "=r"((R)[1]) : "r"(ADDR))

// ---------------------------------------------------------------------------
// Kernel 0a: split weights fp32 -> fp16 hi + scaled lo residual
// ---------------------------------------------------------------------------
__global__ __launch_bounds__(512) void r13_wsplit(
    const float* __restrict__ wq, const float* __restrict__ wk, const float* __restrict__ wv)
{
    int idx = blockIdx.x * 512 + threadIdx.x;          // [0, 3*65536)
    const float* src = (idx < 65536) ? wq : (idx < 131072 ? wk : wv);
    float v = src[idx & 65535];
    __half h, l;
    split_hi_lo(v, h, l);
    g_whi[idx] = h;
    g_wlo[idx] = l;
}

// ---------------------------------------------------------------------------
// Kernel 0b: split + transpose x: [n][c][p] fp32 -> [n][p][c] fp16 hi/lo.
// Block handles a 64c x 64p tile via smem. Grid: (16, 4, 64), 256 threads.
// Tile row stride 68 floats = 272 B (multiple of 16) -> float4 stores are
// aligned for every row (65-stride caused the misaligned-address trap).
// ---------------------------------------------------------------------------
__global__ __launch_bounds__(256) void r13_xsplit(const float* __restrict__ x)
{
    __shared__ __align__(16) float tile[64][68];
    const int pt = blockIdx.x * 64;
    const int ct = blockIdx.y * 64;
    const int n  = blockIdx.z;
    const int t  = threadIdx.x;

    const float* __restrict__ xn = x + (size_t)n * CP;

    // load 64 c-rows x 64 p floats, coalesced
    {
        int c   = t >> 2;
        int pc0 = (t & 3) * 16;
        const float* src = xn + (size_t)(ct + c) * PP + pt + pc0;
        #pragma unroll
        for (int u = 0; u < 4; u++)
            *(float4*)&tile[c][pc0 + u * 4] = *(const float4*)(src + u * 4);
    }
    __syncthreads();

    // write transposed: thread -> p row (t>>2), 16 c values ((t&3)*16)
    {
        int p   = t >> 2;
        int cc0 = (t & 3) * 16;
        __align__(16) __half hbuf[16], lbuf[16];
        #pragma unroll
        for (int u = 0; u < 16; u++) {
            __half h, l;
            split_hi_lo(tile[cc0 + u][p], h, l);
            hbuf[u] = h; lbuf[u] = l;
        }
        size_t dst = (size_t)n * PP * CC + (size_t)(pt + p) * CC + ct + cc0;
        *(uint4*)(g_xthi + dst)     = *(uint4*)hbuf;
        *(uint4*)(g_xthi + dst + 8) = *(uint4*)(hbuf + 8);
        *(uint4*)(g_xtlo + dst)     = *(uint4*)lbuf;
        *(uint4*)(g_xtlo + dst + 8) = *(uint4*)(lbuf + 8);
    }
}

// ---------------------------------------------------------------------------
// Kernel 1: QKV projection GEMM, mma.sync m16n8k16, scaled 3-term split:
//   W.X = Wh.Xh + (Wl.Xh + Wh.Xl) * 2^-11   (+O(2^-20), dropped)
// Grid: (pt, m*2+dh, n) = (8, 6, 64). CTA: C[128d x 128p], K=256 in 8
// chunks of 32, double-buffered. B loaded pre-split & pre-transposed.
// ---------------------------------------------------------------------------
#define TILE_H 5120   // halves per tile (128*40)
#define PROJ_SMEM 81920

__global__ __launch_bounds__(256, 1) void r13_proj(
    const float* __restrict__ x,
    const float* __restrict__ bq,
    const float* __restrict__ bk,
    const float* __restrict__ bv)
{
    extern __shared__ __align__(16) __half sh[];
    __half* As = sh;               // [buf][hl][TILE_H]
    __half* Bs = sh + 4 * TILE_H;  // [buf][hl][TILE_H]

    const int p0 = blockIdx.x * 128;        // 0..7  (p tile)
    const int m  = blockIdx.y >> 1;         // 0..2  (q,k,v)
    const int d0 = (blockIdx.y & 1) * 128;  // 0 or 128  (d half)
    const int n  = blockIdx.z;              // 0..63
    const int t  = threadIdx.x;
    const int lane = t & 31;
    const int wid  = t >> 5;
    const int wm   = wid & 1;               // 0..1 (64 d each)
    const int wn   = wid >> 1;              // 0..3 (32 p each)

    const __half* __restrict__ whp = g_whi + (size_t)m * 65536;
    const __half* __restrict__ wlp = g_wlo + (size_t)m * 65536;

    float chi[4][4][4], clo[4][4][4];
    #pragma unroll
    for (int mi = 0; mi < 4; mi++)
        #pragma unroll
        for (int ni = 0; ni < 4; ni++)
            #pragma unroll
            for (int r = 0; r < 4; r++) { chi[mi][ni][r] = 0.f; clo[mi][ni][r] = 0.f; }

    const int arow = t >> 1;              // 0..127 (d row within block)
    const int acol = (t & 1) * 16;        // half offset within 32-wide K chunk
    const int brow = t >> 1;              // 0..127 (p row)
    const int bseg = (t & 1) * 16;        // half offset within 32-wide c chunk

    const __half* __restrict__ bhbase =
        g_xthi + (size_t)n * PP * CC + (size_t)(p0 + brow) * CC + bseg;
    const __half* __restrict__ blbase =
        g_xtlo + (size_t)n * PP * CC + (size_t)(p0 + brow) * CC + bseg;

    uint4 rah0, rah1, ral0, ral1;
    uint4 rbh0, rbh1, rbl0, rbl1;

    #define TA_LDG(kc)                                                          \
        do {                                                                    \
            size_t wo = (size_t)(d0 + arow)*256 + (kc)*32 + acol;               \
            rah0 = *(const uint4*)(whp + wo);                                   \
            rah1 = *(const uint4*)(whp + wo + 8);                               \
            ral0 = *(const uint4*)(wlp + wo);                                   \
            ral1 = *(const uint4*)(wlp + wo + 8);                               \
            rbh0 = *(const uint4*)(bhbase + (kc)*32);                           \
            rbh1 = *(const uint4*)(bhbase + (kc)*32 + 8);                       \
            rbl0 = *(const uint4*)(blbase + (kc)*32);                           \
            rbl1 = *(const uint4*)(blbase + (kc)*32 + 8);                       \
        } while (0)

    #define TA_STS(buf)                                                         \
        do {                                                                    \
            __half* ah = As + (buf)*2*TILE_H;                                   \
            __half* al = ah + TILE_H;                                           \
            *(uint4*)&ah[arow*40 + acol]     = rah0;                            \
            *(uint4*)&ah[arow*40 + acol + 8] = rah1;                            \
            *(uint4*)&al[arow*40 + acol]     = ral0;                            \
            *(uint4*)&al[arow*40 + acol + 8] = ral1;                            \
            __half* bh = Bs + (buf)*2*TILE_H;                                   \
            __half* bl = bh + TILE_H;                                           \
            *(uint4*)&bh[brow*40 + bseg]     = rbh0;                            \
            *(uint4*)&bh[brow*40 + bseg + 8] = rbh1;                            \
            *(uint4*)&bl[brow*40 + bseg]     = rbl0;                            \
            *(uint4*)&bl[brow*40 + bseg + 8] = rbl1;                            \
        } while (0)

    TA_LDG(0);
    TA_STS(0);
    __syncthreads();

    #pragma unroll 1
    for (int kc = 0; kc < 8; kc++) {
        if (kc < 7) TA_LDG(kc + 1);

        const uint32_t ah_s = smem_u32(As + (kc & 1)*2*TILE_H);
        const uint32_t al_s = ah_s + TILE_H*2;
        const uint32_t bh_s = smem_u32(Bs + (kc & 1)*2*TILE_H);
        const uint32_t bl_s = bh_s + TILE_H*2;

        #pragma unroll
        for (int ks = 0; ks < 2; ks++) {
            const uint32_t a_off = (uint32_t)((wm*64 + (lane & 15))*40 + ks*16 + (lane >> 4)*8) * 2;
            const uint32_t b_off = (uint32_t)((wn*32 + (lane & 7))*40 + ks*16 + ((lane >> 3) & 1)*8) * 2;

            uint32_t afh[4][4], afl[4][4], bfh[4][2], bfl[4][2];
            #pragma unroll
            for (int mi = 0; mi < 4; mi++) {
                LDMX4(afh[mi], ah_s + a_off + (uint32_t)(mi*16*40)*2);
                LDMX4(afl[mi], al_s + a_off + (uint32_t)(mi*16*40)*2);
            }
            #pragma unroll
            for (int ni = 0; ni < 4; ni++) {
                LDMX2(bfh[ni], bh_s + b_off + (uint32_t)(ni*8*40)*2);
                LDMX2(bfl[ni], bl_s + b_off + (uint32_t)(ni*8*40)*2);
            }
            #pragma unroll
            for (int mi = 0; mi < 4; mi++)
                #pragma unroll
                for (int ni = 0; ni < 4; ni++) {
                    MMA16816(chi[mi][ni], afh[mi], bfh[ni]);
                    MMA16816(clo[mi][ni], afl[mi], bfh[ni]);
                    MMA16816(clo[mi][ni], afh[mi], bfl[ni]);
                }
        }

        if (kc < 7) TA_STS((kc + 1) & 1);
        __syncthreads();
    }

    // ---- epilogue: combine hi + lo*2^-11, add bias, store fp32
    const float* __restrict__ bias = (m == 0) ? bq : (m == 1) ? bk : bv;
    float* __restrict__ ob = (m == 0) ? g_q : (m == 1) ? g_k : g_v;
    const int gid = lane >> 2, tid4 = lane & 3;
    const int col = p0 + wn*32 + tid4*2;

    #pragma unroll
    for (int mi = 0; mi < 4; mi++) {
        int d_r = d0 + wm*64 + mi*16 + gid;
        float b0 = bias[d_r];
        float b1 = bias[d_r + 8];
        float* o0 = ob + (size_t)n*CP + (size_t)d_r*PP + col;
        float* o1 = o0 + (size_t)8*PP;
        #pragma unroll
        for (int ni = 0; ni < 4; ni++) {
            float r0 = fmaf(clo[mi][ni][0], LO_INV, chi[mi][ni][0]) + b0;
            float r1 = fmaf(clo[mi][ni][1], LO_INV, chi[mi][ni][1]) + b0;
            float r2 = fmaf(clo[mi][ni][2], LO_INV, chi[mi][ni][2]) + b1;
            float r3 = fmaf(clo[mi][ni][3], LO_INV, chi[mi][ni][3]) + b1;
            *(float2*)(o0 + ni*8) = make_float2(r0, r1);
            *(float2*)(o1 + ni*8) = make_float2(r2, r3);
        }
    }
    #undef TA_LDG
    #undef TA_STS
}

// ---------------------------------------------------------------------------
// Kernel 2: per-(b,c) temporal attention, chunked q/k staging (unchanged).
// ---------------------------------------------------------------------------
#define QS 264

__global__ __launch_bounds__(256, 2) void r13_attn(
    const float* __restrict__ x,
    const float* __restrict__ gamma,
    float* __restrict__ out)
{
    __shared__ float qs[16][QS];
    __shared__ float ks[16][QS];
    __shared__ float S[16][17];
    __shared__ float Pm[16][16];

    const int bc = blockIdx.x;
    const int b  = bc >> 8;
    const int c  = bc & 255;
    const int t  = threadIdx.x;

    const size_t qbase = (size_t)(b * 16) * CP + (size_t)c * PP;

    const int i = t >> 4, j = t & 15;
    float s0 = 0.f, s1 = 0.f, s2 = 0.f, s3 = 0.f;
    #pragma unroll 1
    for (int ch = 0; ch < 4; ch++) {
        __syncthreads();
        {
            int fr = t >> 4, q0 = t & 15;
            size_t base = qbase + (size_t)fr * CP + ch * 256;
            #pragma unroll
            for (int u = 0; u < 4; u++) {
                *(float4*)&qs[fr][(q0 + u * 16) * 4] = *(const float4*)&g_q[base + (q0 + u * 16) * 4];
                *(float4*)&ks[fr][(q0 + u * 16) * 4] = *(const float4*)&g_k[base + (q0 + u * 16) * 4];
            }
        }
        __syncthreads();
        const float* qp = &qs[i][0];
        const float* kp = &ks[j][0];
        #pragma unroll 8
        for (int p = 0; p < 256; p += 4) {
            float4 a = *(const float4*)&qp[p];
            float4 bb = *(const float4*)&kp[p];
            s0 += a.x * bb.x; s1 += a.y * bb.y; s2 += a.z * bb.z; s3 += a.w * bb.w;
        }
    }
    S[i][j] = (s0 + s1) + (s2 + s3);
    __syncthreads();

    if (t < 16) {
        float mx = -1e30f;
        float e[16];
        #pragma unroll
        for (int jj = 0; jj < 16; jj++) {
            float v = S[t][jj] * 0.0625f;
            e[jj] = v;
            mx = fmaxf(mx, v);
        }
        float sum = 0.f;
        #pragma unroll
        for (int jj = 0; jj < 16; jj++) { e[jj] = __expf(e[jj] - mx); sum += e[jj]; }
        float inv = 1.f / sum;
        #pragma unroll
        for (int jj = 0; jj < 16; jj++) Pm[t][jj] = e[jj] * inv;
    }
    __syncthreads();

    float acc[16][4];
    #pragma unroll
    for (int ii = 0; ii < 16; ii++)
        #pragma unroll
        for (int pc = 0; pc < 4; pc++) acc[ii][pc] = 0.f;

    #pragma unroll 1
    for (int jj = 0; jj < 16; jj++) {
        const float* vp = &g_v[qbase + (size_t)jj * CP];
        float v0 = vp[t + 0 * 256];
        float v1 = vp[t + 1 * 256];
        float v2 = vp[t + 2 * 256];
        float v3 = vp[t + 3 * 256];
        #pragma unroll
        for (int ii = 0; ii < 16; ii++) {
            float pij = Pm[ii][jj];
            acc[ii][0] += pij * v0;
            acc[ii][1] += pij * v1;
            acc[ii][2] += pij * v2;
            acc[ii][3] += pij * v3;
        }
    }

    const float g = gamma[0];
    const size_t xbase = (size_t)b * CFP + (size_t)c * (FF * PP);
    #pragma unroll
    for (int ii = 0; ii < 16; ii++) {
        #pragma unroll
        for (int pc = 0; pc < 4; pc++) {
            size_t idx = xbase + (size_t)ii * PP + t + pc * 256;
            out[idx] = g * acc[ii][pc] + x[idx];
        }
    }
}

// ---------------------------------------------------------------------------
extern "C" void kernel_launch(void* const* d_in, const int* in_sizes, int n_in,
                              void* d_out, int out_size)
{
    const float* x     = (const float*)d_in[0];
    const float* wq    = (const float*)d_in[1];
    const float* bq    = (const float*)d_in[2];
    const float* wk    = (const float*)d_in[3];
    const float* bk    = (const float*)d_in[4];
    const float* wv    = (const float*)d_in[5];
    const float* bv    = (const float*)d_in[6];
    const float* gamma = (const float*)d_in[7];
    float* out = (float*)d_out;

    cudaFuncSetAttribute(r13_proj,
                         cudaFuncAttributeMaxDynamicSharedMemorySize, PROJ_SMEM);

    r13_wsplit<<<384, 512>>>(wq, wk, wv);
    r13_xsplit<<<dim3(16, 4, 64), 256>>>(x);
    r13_proj<<<dim3(8, 6, 64), 256, PROJ_SMEM>>>(x, bq, bk, bv);
    r13_attn<<<BB*CC, 256>>>(x, gamma, out);
}